// round 1
// baseline (speedup 1.0000x reference)
#include <cuda_runtime.h>
#include <math.h>

// ---------------------------------------------------------------------------
// NAT Global Transformer block, fp32 baseline.
// B=2, IMG=112, CIN=64, C=256, HEADS=8, HD=32, K=3
// ---------------------------------------------------------------------------

constexpr int Bn    = 2;
constexpr int Hc    = 112;
constexpr int Wc    = 112;
constexpr int CIN   = 64;
constexpr int C     = 256;
constexpr int HEADS = 8;
constexpr int HD    = 32;
constexpr int HW    = Hc * Wc;        // 12544
constexpr int M     = Bn * HW;        // 25088
constexpr int KC    = CIN * 9;        // 576  (im2col K)

// ---------------- scratch (static device arrays; no allocation) ------------
__device__ float g_x1[M * C];                 // conv1 out, NHWC
__device__ float g_x3[M * C];                 // conv3 out, NHWC
__device__ float g_qkv[M * 3 * C];            // [m][q|k|v] (768 cols)
__device__ float g_attn[M * C];               // attention out (pre-proj)
__device__ float g_att[M * C];                // proj + x3 residual
__device__ float g_mlp[M * 2 * C];            // gelu(fc1)
__device__ float g_stats1[M * 2];             // mean,rstd of x1
__device__ float g_stats3[M * 2];             // mean,rstd of att
__device__ float g_wt1[KC * C];               // conv1 weights, [k][co]
__device__ float g_wt3[KC * C];
__device__ float g_wqkv[C * 3 * C];           // LN-folded [wq*scale | wkv]
__device__ float g_bqkv[3 * C];
__device__ float g_wfc1[C * 2 * C];           // LN3-folded fc1
__device__ float g_bfc1[2 * C];

// ---------------------------------------------------------------------------
// Weight preprocessing
// ---------------------------------------------------------------------------
__global__ void transpose_convw(const float* __restrict__ w, float* __restrict__ wt) {
    int idx = blockIdx.x * 256 + threadIdx.x;      // KC*C = 147456
    if (idx < KC * C) {
        int k = idx / C, co = idx % C;
        wt[idx] = w[co * KC + k];                  // OIHW -> [k][co]
    }
}

// fold LN affine + q-scale into the qkv weight matrix
__global__ void fold_qkv(const float* __restrict__ wq, const float* __restrict__ bq,
                         const float* __restrict__ wkv, const float* __restrict__ bkv,
                         const float* __restrict__ w1, const float* __restrict__ b1,
                         const float* __restrict__ w10, const float* __restrict__ b10) {
    __shared__ float red[256];
    int n = blockIdx.x;          // 0..767
    int i = threadIdx.x;         // 0..255
    float scale = 1.0f / sqrtf((float)HD);
    float we, bc;
    if (n < C) {
        float w = wq[i * C + n];
        we = w1[i] * w * scale;
        bc = b1[i] * w;
    } else {
        int j = n - C;
        float w = wkv[i * (2 * C) + j];
        we = w10[i] * w;
        bc = b10[i] * w;
    }
    g_wqkv[i * (3 * C) + n] = we;
    red[i] = bc;
    __syncthreads();
    for (int s = 128; s > 0; s >>= 1) {
        if (i < s) red[i] += red[i + s];
        __syncthreads();
    }
    if (i == 0) {
        if (n < C) g_bqkv[n] = (red[0] + bq[n]) * scale;
        else       g_bqkv[n] = red[0] + bkv[n - C];
    }
}

__global__ void fold_fc1(const float* __restrict__ fc1_w, const float* __restrict__ fc1_b,
                         const float* __restrict__ w3, const float* __restrict__ b3) {
    __shared__ float red[256];
    int n = blockIdx.x;          // 0..511
    int i = threadIdx.x;         // 0..255
    float w = fc1_w[i * (2 * C) + n];
    g_wfc1[i * (2 * C) + n] = w3[i] * w;
    red[i] = b3[i] * w;
    __syncthreads();
    for (int s = 128; s > 0; s >>= 1) {
        if (i < s) red[i] += red[i + s];
        __syncthreads();
    }
    if (i == 0) g_bfc1[n] = red[0] + fc1_b[n];
}

// ---------------------------------------------------------------------------
// LayerNorm stats: one warp per pixel (C=256)
// ---------------------------------------------------------------------------
__global__ void ln_stats(const float* __restrict__ x, float* __restrict__ stats) {
    int m = blockIdx.x * 8 + (threadIdx.x >> 5);
    int lane = threadIdx.x & 31;
    const float4* p = reinterpret_cast<const float4*>(x + (size_t)m * C);
    float4 u0 = p[lane];
    float4 u1 = p[lane + 32];
    float s  = u0.x + u0.y + u0.z + u0.w + u1.x + u1.y + u1.z + u1.w;
    float ss = u0.x*u0.x + u0.y*u0.y + u0.z*u0.z + u0.w*u0.w
             + u1.x*u1.x + u1.y*u1.y + u1.z*u1.z + u1.w*u1.w;
    #pragma unroll
    for (int o = 16; o > 0; o >>= 1) {
        s  += __shfl_xor_sync(0xFFFFFFFFu, s, o);
        ss += __shfl_xor_sync(0xFFFFFFFFu, ss, o);
    }
    if (lane == 0) {
        float mu  = s * (1.0f / C);
        float var = ss * (1.0f / C) - mu * mu;
        stats[2 * m]     = mu;
        stats[2 * m + 1] = rsqrtf(var + 1e-5f);
    }
}

// ---------------------------------------------------------------------------
// Generic SGEMM: 128x64 tile, BK=16, 256 threads, 8x4 per-thread microtile.
// ALOADER: 0 = plain row-major A[M][KDIM]
//          1 = implicit im2col conv (A = NCHW input)
//          2 = LN-normalized plain A ((x-mu)*rstd per row)
// EPI:     0 = +bias
//          1 = +bias + residual
//          2 = +bias, GELU(exact)
//          3 = +bias + residual, store NCHW-transposed
// ---------------------------------------------------------------------------
__device__ __forceinline__ float gelu_exact(float x) {
    return 0.5f * x * (1.0f + erff(x * 0.70710678118654752440f));
}

template <int ALOADER, int EPI, int KDIM, int NDIM>
__global__ void __launch_bounds__(256)
gemm_kernel(const float* __restrict__ A, const float* __restrict__ Bm,
            const float* __restrict__ bias, const float* __restrict__ stats,
            const float* __restrict__ res, float* __restrict__ out) {
    constexpr int BM = 128, BN = 64, BK = 16;
    __shared__ float As[BK][BM];
    __shared__ float Bs[BK][BN];

    int tid = threadIdx.x;
    int bm = blockIdx.x * BM;
    int bn = blockIdx.y * BN;
    int tx = tid & 15;            // n micro (4 cols)
    int ty = tid >> 4;            // m micro (8 rows)

    // A-load mapping: each thread loads 8 consecutive k for one m
    int a_m = tid & 127;
    int a_k = (tid >> 7) * 8;     // 0 or 8
    int gm  = bm + a_m;

    // B-load mapping
    int b_n = (tid & 15) * 4;
    int b_k = tid >> 4;

    int bb = 0, hh = 0, ww = 0;
    if (ALOADER == 1) {
        bb = gm / HW;
        int r = gm % HW;
        hh = r / Wc;
        ww = r % Wc;
    }
    float mu = 0.f, rs = 1.f;
    if (ALOADER == 2) {
        mu = stats[2 * gm];
        rs = stats[2 * gm + 1];
    }

    float acc[8][4];
    #pragma unroll
    for (int i = 0; i < 8; i++)
        #pragma unroll
        for (int j = 0; j < 4; j++) acc[i][j] = 0.f;

    for (int k0 = 0; k0 < KDIM; k0 += BK) {
        float av[8];
        if (ALOADER == 1) {
            #pragma unroll
            for (int i = 0; i < 8; i++) {
                int k = k0 + a_k + i;
                int cin = k / 9;
                int t   = k - cin * 9;
                int rr = hh + t / 3 - 1;
                int cc = ww + t % 3 - 1;
                av[i] = (rr >= 0 && rr < Hc && cc >= 0 && cc < Wc)
                        ? A[((size_t)(bb * CIN + cin) * Hc + rr) * Wc + cc] : 0.f;
            }
        } else {
            const float4* ap = reinterpret_cast<const float4*>(A + (size_t)gm * KDIM + k0 + a_k);
            float4 l0 = ap[0];
            float4 l1 = ap[1];
            av[0] = l0.x; av[1] = l0.y; av[2] = l0.z; av[3] = l0.w;
            av[4] = l1.x; av[5] = l1.y; av[6] = l1.z; av[7] = l1.w;
            if (ALOADER == 2) {
                #pragma unroll
                for (int i = 0; i < 8; i++) av[i] = (av[i] - mu) * rs;
            }
        }
        #pragma unroll
        for (int i = 0; i < 8; i++) As[a_k + i][a_m] = av[i];

        float4 bv = *reinterpret_cast<const float4*>(Bm + (size_t)(k0 + b_k) * NDIM + bn + b_n);
        *reinterpret_cast<float4*>(&Bs[b_k][b_n]) = bv;

        __syncthreads();
        #pragma unroll
        for (int kk = 0; kk < BK; kk++) {
            float af[8], bf[4];
            #pragma unroll
            for (int i = 0; i < 8; i++) af[i] = As[kk][ty * 8 + i];
            #pragma unroll
            for (int j = 0; j < 4; j++) bf[j] = Bs[kk][tx * 4 + j];
            #pragma unroll
            for (int i = 0; i < 8; i++)
                #pragma unroll
                for (int j = 0; j < 4; j++) acc[i][j] += af[i] * bf[j];
        }
        __syncthreads();
    }

    #pragma unroll
    for (int i = 0; i < 8; i++) {
        int m = bm + ty * 8 + i;
        int mb = m / HW;
        int mp = m - mb * HW;
        #pragma unroll
        for (int j = 0; j < 4; j++) {
            int n = bn + tx * 4 + j;
            float v = acc[i][j] + bias[n];
            if constexpr (EPI == 1 || EPI == 3) v += res[(size_t)m * NDIM + n];
            if constexpr (EPI == 2) v = gelu_exact(v);
            if constexpr (EPI == 3) {
                out[((size_t)mb * C + n) * HW + mp] = v;   // NCHW store
            } else {
                out[(size_t)m * NDIM + n] = v;
            }
        }
    }
}

// ---------------------------------------------------------------------------
// 3x3 neighborhood attention. One block = (8x8 pixel tile, one head, one b).
// k/v halo (10x10 positions x 32 dims) staged in smem.
// ---------------------------------------------------------------------------
__global__ void __launch_bounds__(64)
nat_attn(const float* __restrict__ rpb) {
    __shared__ float ks[100 * 33];
    __shared__ float vs[100 * 33];

    int ti = blockIdx.x / 14;
    int tj = blockIdx.x % 14;
    int head = blockIdx.y;
    int b = blockIdx.z;
    int tid = threadIdx.x;

    int r0 = ti * 8 - 1;
    int c0 = tj * 8 - 1;

    // halo load: 100 positions x 8 float4 chunks
    for (int idx = tid; idx < 100 * 8; idx += 64) {
        int pos = idx >> 3;
        int d0  = (idx & 7) * 4;
        int rr = pos / 10, cc = pos % 10;
        int gi = r0 + rr, gj = c0 + cc;
        float4 kv = make_float4(0.f, 0.f, 0.f, 0.f);
        float4 vv = make_float4(0.f, 0.f, 0.f, 0.f);
        if (gi >= 0 && gi < Hc && gj >= 0 && gj < Wc) {
            size_t base = (size_t)(b * HW + gi * Wc + gj) * (3 * C) + head * HD + d0;
            kv = *reinterpret_cast<const float4*>(g_qkv + base + C);
            vv = *reinterpret_cast<const float4*>(g_qkv + base + 2 * C);
        }
        float* kp = ks + pos * 33 + d0;
        float* vp = vs + pos * 33 + d0;
        kp[0] = kv.x; kp[1] = kv.y; kp[2] = kv.z; kp[3] = kv.w;
        vp[0] = vv.x; vp[1] = vv.y; vp[2] = vv.z; vp[3] = vv.w;
    }
    __syncthreads();

    int li = tid >> 3, lj = tid & 7;
    int i = ti * 8 + li;
    int j = tj * 8 + lj;
    int si = min(max(i - 1, 0), Hc - 3);
    int sj = min(max(j - 1, 0), Wc - 3);
    int pi = i - si;
    int pj = j - sj;
    int pbase = (si - r0) * 10 + (sj - c0);

    size_t mq = (size_t)(b * HW + i * Wc + j) * (3 * C) + head * HD;
    float q[HD];
    #pragma unroll
    for (int d = 0; d < HD; d += 4) {
        float4 u = *reinterpret_cast<const float4*>(g_qkv + mq + d);
        q[d] = u.x; q[d + 1] = u.y; q[d + 2] = u.z; q[d + 3] = u.w;
    }

    const float* rp = rpb + head * 25;
    float logits[9];
    #pragma unroll
    for (int a = 0; a < 3; a++)
        #pragma unroll
        for (int c = 0; c < 3; c++) {
            const float* kk = ks + (pbase + a * 10 + c) * 33;
            float s = 0.f;
            #pragma unroll
            for (int d = 0; d < HD; d++) s += q[d] * kk[d];
            logits[a * 3 + c] = s + rp[(a - pi + 2) * 5 + (c - pj + 2)];
        }

    float mx = logits[0];
    #pragma unroll
    for (int n = 1; n < 9; n++) mx = fmaxf(mx, logits[n]);
    float wsum = 0.f;
    float wgt[9];
    #pragma unroll
    for (int n = 0; n < 9; n++) { wgt[n] = expf(logits[n] - mx); wsum += wgt[n]; }
    float inv = 1.0f / wsum;

    float o[HD];
    #pragma unroll
    for (int d = 0; d < HD; d++) o[d] = 0.f;
    #pragma unroll
    for (int n = 0; n < 9; n++) {
        float wn = wgt[n] * inv;
        const float* vv = vs + (pbase + (n / 3) * 10 + (n % 3)) * 33;
        #pragma unroll
        for (int d = 0; d < HD; d++) o[d] += wn * vv[d];
    }

    size_t mo = (size_t)(b * HW + i * Wc + j) * C + head * HD;
    #pragma unroll
    for (int d = 0; d < HD; d += 4) {
        *reinterpret_cast<float4*>(g_attn + mo + d) = make_float4(o[d], o[d + 1], o[d + 2], o[d + 3]);
    }
}

// ---------------------------------------------------------------------------
// Launch
// ---------------------------------------------------------------------------
extern "C" void kernel_launch(void* const* d_in, const int* in_sizes, int n_in,
                              void* d_out, int out_size) {
    const float* xq      = (const float*)d_in[0];
    const float* xkv     = (const float*)d_in[1];
    const float* conv1_w = (const float*)d_in[2];
    const float* conv1_b = (const float*)d_in[3];
    const float* conv3_w = (const float*)d_in[4];
    const float* conv3_b = (const float*)d_in[5];
    const float* ln1_w   = (const float*)d_in[6];
    const float* ln1_b   = (const float*)d_in[7];
    const float* ln10_w  = (const float*)d_in[8];
    const float* ln10_b  = (const float*)d_in[9];
    const float* ln3_w   = (const float*)d_in[10];
    const float* ln3_b   = (const float*)d_in[11];
    const float* wq      = (const float*)d_in[12];
    const float* bq      = (const float*)d_in[13];
    const float* wkv     = (const float*)d_in[14];
    const float* bkv     = (const float*)d_in[15];
    const float* rpb     = (const float*)d_in[16];
    const float* wp      = (const float*)d_in[17];
    const float* bp      = (const float*)d_in[18];
    const float* fc1_w   = (const float*)d_in[19];
    const float* fc1_b   = (const float*)d_in[20];
    const float* fc2_w   = (const float*)d_in[21];
    const float* fc2_b   = (const float*)d_in[22];
    float* out = (float*)d_out;

    // resolve scratch symbol addresses (pure lookup; capture-safe)
    float *p_x1, *p_x3, *p_qkv, *p_attn, *p_att, *p_mlp,
          *p_st1, *p_st3, *p_wt1, *p_wt3, *p_wqkv, *p_bqkv, *p_wfc1, *p_bfc1;
    cudaGetSymbolAddress((void**)&p_x1, g_x1);
    cudaGetSymbolAddress((void**)&p_x3, g_x3);
    cudaGetSymbolAddress((void**)&p_qkv, g_qkv);
    cudaGetSymbolAddress((void**)&p_attn, g_attn);
    cudaGetSymbolAddress((void**)&p_att, g_att);
    cudaGetSymbolAddress((void**)&p_mlp, g_mlp);
    cudaGetSymbolAddress((void**)&p_st1, g_stats1);
    cudaGetSymbolAddress((void**)&p_st3, g_stats3);
    cudaGetSymbolAddress((void**)&p_wt1, g_wt1);
    cudaGetSymbolAddress((void**)&p_wt3, g_wt3);
    cudaGetSymbolAddress((void**)&p_wqkv, g_wqkv);
    cudaGetSymbolAddress((void**)&p_bqkv, g_bqkv);
    cudaGetSymbolAddress((void**)&p_wfc1, g_wfc1);
    cudaGetSymbolAddress((void**)&p_bfc1, g_bfc1);

    // 1. weight preprocessing
    transpose_convw<<<(KC * C + 255) / 256, 256>>>(conv1_w, p_wt1);
    transpose_convw<<<(KC * C + 255) / 256, 256>>>(conv3_w, p_wt3);
    fold_qkv<<<3 * C, 256>>>(wq, bq, wkv, bkv, ln1_w, ln1_b, ln10_w, ln10_b);
    fold_fc1<<<2 * C, 256>>>(fc1_w, fc1_b, ln3_w, ln3_b);

    dim3 gemm_block(256);
    // 2. convs (implicit im2col GEMM)
    gemm_kernel<1, 0, KC, C><<<dim3(M / 128, C / 64), gemm_block>>>(
        xq, p_wt1, conv1_b, nullptr, nullptr, p_x1);
    gemm_kernel<1, 0, KC, C><<<dim3(M / 128, C / 64), gemm_block>>>(
        xkv, p_wt3, conv3_b, nullptr, nullptr, p_x3);

    // 3. LN stats for x1
    ln_stats<<<M / 8, 256>>>(p_x1, p_st1);

    // 4. fused LN + qkv projection
    gemm_kernel<2, 0, C, 3 * C><<<dim3(M / 128, (3 * C) / 64), gemm_block>>>(
        p_x1, p_wqkv, p_bqkv, p_st1, nullptr, p_qkv);

    // 5. neighborhood attention
    nat_attn<<<dim3(14 * 14, HEADS, Bn), 64>>>(rpb);

    // 6. output projection + x3 residual
    gemm_kernel<0, 1, C, C><<<dim3(M / 128, C / 64), gemm_block>>>(
        p_attn, wp, bp, nullptr, p_x3, p_att);

    // 7. LN stats for att
    ln_stats<<<M / 8, 256>>>(p_att, p_st3);

    // 8. fused LN + fc1 + GELU
    gemm_kernel<2, 2, C, 2 * C><<<dim3(M / 128, (2 * C) / 64), gemm_block>>>(
        p_att, p_wfc1, p_bfc1, p_st3, nullptr, p_mlp);

    // 9. fc2 + att residual, NCHW transposed store to output
    gemm_kernel<0, 3, 2 * C, C><<<dim3(M / 128, C / 64), gemm_block>>>(
        p_mlp, fc2_w, fc2_b, nullptr, p_att, out);
}

// round 2
// speedup vs baseline: 2.1485x; 2.1485x over previous
#include <cuda_runtime.h>
#include <math.h>
#include <stdint.h>

// ---------------------------------------------------------------------------
// NAT Global Transformer block. Round 2: all GEMMs on tf32 tensor cores.
// B=2, IMG=112, CIN=64, C=256, HEADS=8, HD=32, K=3
// ---------------------------------------------------------------------------

constexpr int Bn    = 2;
constexpr int Hc    = 112;
constexpr int Wc    = 112;
constexpr int CIN   = 64;
constexpr int C     = 256;
constexpr int HEADS = 8;
constexpr int HD    = 32;
constexpr int HW    = Hc * Wc;        // 12544
constexpr int M     = Bn * HW;        // 25088
constexpr int KC    = CIN * 9;        // 576  (im2col K)

// ---------------- scratch (static device arrays; no allocation) ------------
__device__ float g_x1[M * C];                 // conv1 out, NHWC
__device__ float g_x3[M * C];                 // conv3 out, NHWC
__device__ float g_qkv[M * 3 * C];            // [m][q|k|v] (768 cols)
__device__ float g_attn[M * C];               // attention out (pre-proj)
__device__ float g_att[M * C];                // proj + x3 residual
__device__ float g_mlp[M * 2 * C];            // gelu(fc1)
__device__ float g_stats1[M * 2];             // mean,rstd of x1
__device__ float g_stats3[M * 2];             // mean,rstd of att
__device__ float g_wt1[KC * C];               // conv1 weights, [k][co]
__device__ float g_wt3[KC * C];
__device__ float g_wqkv[C * 3 * C];           // LN-folded [wq*scale | wkv]
__device__ float g_bqkv[3 * C];
__device__ float g_wfc1[C * 2 * C];           // LN3-folded fc1
__device__ float g_bfc1[2 * C];

// ---------------------------------------------------------------------------
// Weight preprocessing
// ---------------------------------------------------------------------------
__global__ void transpose_convw(const float* __restrict__ w, float* __restrict__ wt) {
    int idx = blockIdx.x * 256 + threadIdx.x;      // KC*C = 147456
    if (idx < KC * C) {
        int k = idx / C, co = idx % C;
        wt[idx] = w[co * KC + k];                  // OIHW -> [k][co]
    }
}

__global__ void fold_qkv(const float* __restrict__ wq, const float* __restrict__ bq,
                         const float* __restrict__ wkv, const float* __restrict__ bkv,
                         const float* __restrict__ w1, const float* __restrict__ b1,
                         const float* __restrict__ w10, const float* __restrict__ b10) {
    __shared__ float red[256];
    int n = blockIdx.x;          // 0..767
    int i = threadIdx.x;         // 0..255
    float scale = 1.0f / sqrtf((float)HD);
    float we, bc;
    if (n < C) {
        float w = wq[i * C + n];
        we = w1[i] * w * scale;
        bc = b1[i] * w;
    } else {
        int j = n - C;
        float w = wkv[i * (2 * C) + j];
        we = w10[i] * w;
        bc = b10[i] * w;
    }
    g_wqkv[i * (3 * C) + n] = we;
    red[i] = bc;
    __syncthreads();
    for (int s = 128; s > 0; s >>= 1) {
        if (i < s) red[i] += red[i + s];
        __syncthreads();
    }
    if (i == 0) {
        if (n < C) g_bqkv[n] = (red[0] + bq[n]) * scale;
        else       g_bqkv[n] = red[0] + bkv[n - C];
    }
}

__global__ void fold_fc1(const float* __restrict__ fc1_w, const float* __restrict__ fc1_b,
                         const float* __restrict__ w3, const float* __restrict__ b3) {
    __shared__ float red[256];
    int n = blockIdx.x;          // 0..511
    int i = threadIdx.x;         // 0..255
    float w = fc1_w[i * (2 * C) + n];
    g_wfc1[i * (2 * C) + n] = w3[i] * w;
    red[i] = b3[i] * w;
    __syncthreads();
    for (int s = 128; s > 0; s >>= 1) {
        if (i < s) red[i] += red[i + s];
        __syncthreads();
    }
    if (i == 0) g_bfc1[n] = red[0] + fc1_b[n];
}

// ---------------------------------------------------------------------------
// LayerNorm stats
// ---------------------------------------------------------------------------
__global__ void ln_stats(const float* __restrict__ x, float* __restrict__ stats) {
    int m = blockIdx.x * 8 + (threadIdx.x >> 5);
    int lane = threadIdx.x & 31;
    const float4* p = reinterpret_cast<const float4*>(x + (size_t)m * C);
    float4 u0 = p[lane];
    float4 u1 = p[lane + 32];
    float s  = u0.x + u0.y + u0.z + u0.w + u1.x + u1.y + u1.z + u1.w;
    float ss = u0.x*u0.x + u0.y*u0.y + u0.z*u0.z + u0.w*u0.w
             + u1.x*u1.x + u1.y*u1.y + u1.z*u1.z + u1.w*u1.w;
    #pragma unroll
    for (int o = 16; o > 0; o >>= 1) {
        s  += __shfl_xor_sync(0xFFFFFFFFu, s, o);
        ss += __shfl_xor_sync(0xFFFFFFFFu, ss, o);
    }
    if (lane == 0) {
        float mu  = s * (1.0f / C);
        float var = ss * (1.0f / C) - mu * mu;
        stats[2 * m]     = mu;
        stats[2 * m + 1] = rsqrtf(var + 1e-5f);
    }
}

// ---------------------------------------------------------------------------
// tf32 tensor-core GEMM: 128x64x32 block tile, 8 warps, m16n8k8 mma.
// ALOADER: 0 plain, 1 implicit im2col (NCHW input), 2 LN-normalized
// EPI:     0 +bias | 1 +bias+res | 2 +bias,GELU | 3 +bias+res, NCHW store
// ---------------------------------------------------------------------------
__device__ __forceinline__ float gelu_exact(float x) {
    return 0.5f * x * (1.0f + erff(x * 0.70710678118654752440f));
}
__device__ __forceinline__ float f2tf(float x) {
    uint32_t r;
    asm("cvt.rna.tf32.f32 %0, %1;" : "=r"(r) : "f"(x));
    return __uint_as_float(r);
}
__device__ __forceinline__ void ldsm4(uint32_t addr, uint32_t& r0, uint32_t& r1,
                                      uint32_t& r2, uint32_t& r3) {
    asm volatile("ldmatrix.sync.aligned.m8n8.x4.shared.b16 {%0,%1,%2,%3}, [%4];"
                 : "=r"(r0), "=r"(r1), "=r"(r2), "=r"(r3) : "r"(addr));
}
__device__ __forceinline__ void mma_tf32(float c[4], uint32_t a0, uint32_t a1,
                                         uint32_t a2, uint32_t a3,
                                         uint32_t b0, uint32_t b1) {
    asm volatile(
        "mma.sync.aligned.m16n8k8.row.col.f32.tf32.tf32.f32 "
        "{%0,%1,%2,%3}, {%4,%5,%6,%7}, {%8,%9}, {%0,%1,%2,%3};"
        : "+f"(c[0]), "+f"(c[1]), "+f"(c[2]), "+f"(c[3])
        : "r"(a0), "r"(a1), "r"(a2), "r"(a3), "r"(b0), "r"(b1));
}

constexpr int BM = 128, BN = 64, BK = 32;
constexpr int APAD = 4;                      // row stride 36 floats
constexpr int AST = BK + APAD;               // 36
constexpr int BST = BK + APAD;               // 36
constexpr int ASZ = BM * AST;                // floats
constexpr int BSZ = BN * BST;
constexpr int SMEM_BYTES = 2 * (ASZ + BSZ) * 4;   // 55296

template <int ALOADER, int EPI, int KDIM, int NDIM>
__global__ void __launch_bounds__(256, 2)
gemm_tc(const float* __restrict__ A, const float* __restrict__ Bm,
        const float* __restrict__ bias, const float* __restrict__ stats,
        const float* __restrict__ res, float* __restrict__ out) {
    extern __shared__ float smem[];

    int tid  = threadIdx.x;
    int lane = tid & 31;
    int warp = tid >> 5;
    int bm = blockIdx.x * BM;
    int bn = blockIdx.y * BN;
    int wm = (warp & 3) * 32;        // warp m offset in tile
    int wn = (warp >> 2) * 32;       // warp n offset in tile

    // producer mappings
    int a_m  = tid >> 1;             // 0..127
    int a_kq = (tid & 1) * 16;       // 0 or 16
    int gm   = bm + a_m;
    int b_n  = tid & 63;
    int b_k8 = (tid >> 6) * 8;       // 0,8,16,24

    int bb = 0, hh = 0, ww = 0;
    if (ALOADER == 1) {
        bb = gm / HW;
        int r = gm - bb * HW;
        hh = r / Wc;
        ww = r - hh * Wc;
    }
    float mu = 0.f, rs = 1.f;
    if (ALOADER == 2) {
        mu = stats[2 * gm];
        rs = stats[2 * gm + 1];
    }

    // smem fragment addresses (per buffer, ldmatrix lane addressing)
    uint32_t smem_u = (uint32_t)__cvta_generic_to_shared(smem);
    int arow = wm + (lane & 7) + ((lane >> 3) & 1) * 8;
    int acol = ((lane >> 4) & 1) * 4;
    int brow = wn + ((lane >> 4) & 1) * 8 + (lane & 7);
    int bcol = ((lane >> 3) & 1) * 4;

    uint32_t aAddr[2][2], bAddr[2][2];     // [buf][mt / p]
    #pragma unroll
    for (int buf = 0; buf < 2; buf++) {
        uint32_t base = smem_u + buf * (ASZ + BSZ) * 4;
        #pragma unroll
        for (int mt = 0; mt < 2; mt++)
            aAddr[buf][mt] = base + ((arow + mt * 16) * AST + acol) * 4;
        #pragma unroll
        for (int p = 0; p < 2; p++)
            bAddr[buf][p] = base + ASZ * 4 + ((brow + p * 16) * BST + bcol) * 4;
    }

    float acc[2][4][4];
    #pragma unroll
    for (int mt = 0; mt < 2; mt++)
        #pragma unroll
        for (int nt = 0; nt < 4; nt++)
            #pragma unroll
            for (int r = 0; r < 4; r++) acc[mt][nt][r] = 0.f;

    float ra[16], rb[8];

    auto load_gmem = [&](int k0) {
        if (ALOADER == 1) {
            #pragma unroll
            for (int i = 0; i < 16; i++) {
                int k = k0 + a_kq + i;
                int cin = k / 9;
                int t   = k - cin * 9;
                int rr = hh + t / 3 - 1;
                int cc = ww + t % 3 - 1;
                ra[i] = (rr >= 0 && rr < Hc && cc >= 0 && cc < Wc)
                        ? A[((size_t)(bb * CIN + cin) * Hc + rr) * Wc + cc] : 0.f;
            }
        } else {
            const float4* ap = reinterpret_cast<const float4*>(A + (size_t)gm * KDIM + k0 + a_kq);
            #pragma unroll
            for (int v = 0; v < 4; v++) {
                float4 u = ap[v];
                ra[v*4+0] = u.x; ra[v*4+1] = u.y; ra[v*4+2] = u.z; ra[v*4+3] = u.w;
            }
            if (ALOADER == 2) {
                #pragma unroll
                for (int i = 0; i < 16; i++) ra[i] = (ra[i] - mu) * rs;
            }
        }
        #pragma unroll
        for (int j = 0; j < 8; j++)
            rb[j] = Bm[(size_t)(k0 + b_k8 + j) * NDIM + bn + b_n];
    };

    auto store_smem = [&](int buf) {
        float* As = smem + buf * (ASZ + BSZ);
        float* Bs = As + ASZ;
        float4* ad = reinterpret_cast<float4*>(&As[a_m * AST + a_kq]);
        #pragma unroll
        for (int v = 0; v < 4; v++)
            ad[v] = make_float4(f2tf(ra[v*4+0]), f2tf(ra[v*4+1]),
                                f2tf(ra[v*4+2]), f2tf(ra[v*4+3]));
        float4* bd = reinterpret_cast<float4*>(&Bs[b_n * BST + b_k8]);
        bd[0] = make_float4(f2tf(rb[0]), f2tf(rb[1]), f2tf(rb[2]), f2tf(rb[3]));
        bd[1] = make_float4(f2tf(rb[4]), f2tf(rb[5]), f2tf(rb[6]), f2tf(rb[7]));
    };

    auto compute = [&](int buf) {
        #pragma unroll
        for (int ks = 0; ks < 4; ks++) {
            uint32_t a[2][4], b[2][4];
            #pragma unroll
            for (int mt = 0; mt < 2; mt++)
                ldsm4(aAddr[buf][mt] + ks * 32, a[mt][0], a[mt][1], a[mt][2], a[mt][3]);
            #pragma unroll
            for (int p = 0; p < 2; p++)
                ldsm4(bAddr[buf][p] + ks * 32, b[p][0], b[p][1], b[p][2], b[p][3]);
            #pragma unroll
            for (int mt = 0; mt < 2; mt++)
                #pragma unroll
                for (int p = 0; p < 2; p++) {
                    mma_tf32(acc[mt][2*p],   a[mt][0], a[mt][1], a[mt][2], a[mt][3],
                             b[p][0], b[p][1]);
                    mma_tf32(acc[mt][2*p+1], a[mt][0], a[mt][1], a[mt][2], a[mt][3],
                             b[p][2], b[p][3]);
                }
        }
    };

    constexpr int NIT = KDIM / BK;
    load_gmem(0);
    store_smem(0);
    __syncthreads();
    for (int it = 0; it < NIT; ++it) {
        if (it + 1 < NIT) load_gmem((it + 1) * BK);
        compute(it & 1);
        if (it + 1 < NIT) store_smem((it + 1) & 1);
        __syncthreads();
    }

    // epilogue
    int row0 = lane >> 2;
    int col0 = (lane & 3) * 2;
    #pragma unroll
    for (int mt = 0; mt < 2; mt++) {
        #pragma unroll
        for (int half = 0; half < 2; half++) {
            int m = bm + wm + mt * 16 + row0 + half * 8;
            int mb = m / HW;
            int mp = m - mb * HW;
            #pragma unroll
            for (int nt = 0; nt < 4; nt++) {
                int n = bn + wn + nt * 8 + col0;
                float v0 = acc[mt][nt][half * 2 + 0];
                float v1 = acc[mt][nt][half * 2 + 1];
                float2 bi = *reinterpret_cast<const float2*>(&bias[n]);
                v0 += bi.x; v1 += bi.y;
                if constexpr (EPI == 1 || EPI == 3) {
                    float2 rr = *reinterpret_cast<const float2*>(&res[(size_t)m * NDIM + n]);
                    v0 += rr.x; v1 += rr.y;
                }
                if constexpr (EPI == 2) { v0 = gelu_exact(v0); v1 = gelu_exact(v1); }
                if constexpr (EPI == 3) {
                    out[((size_t)mb * C + n) * HW + mp]     = v0;
                    out[((size_t)mb * C + n + 1) * HW + mp] = v1;
                } else {
                    *reinterpret_cast<float2*>(&out[(size_t)m * NDIM + n]) = make_float2(v0, v1);
                }
            }
        }
    }
}

// ---------------------------------------------------------------------------
// 3x3 neighborhood attention (unchanged from round 1)
// ---------------------------------------------------------------------------
__global__ void __launch_bounds__(64)
nat_attn(const float* __restrict__ rpb) {
    __shared__ float ks[100 * 33];
    __shared__ float vs[100 * 33];

    int ti = blockIdx.x / 14;
    int tj = blockIdx.x % 14;
    int head = blockIdx.y;
    int b = blockIdx.z;
    int tid = threadIdx.x;

    int r0 = ti * 8 - 1;
    int c0 = tj * 8 - 1;

    for (int idx = tid; idx < 100 * 8; idx += 64) {
        int pos = idx >> 3;
        int d0  = (idx & 7) * 4;
        int rr = pos / 10, cc = pos % 10;
        int gi = r0 + rr, gj = c0 + cc;
        float4 kv = make_float4(0.f, 0.f, 0.f, 0.f);
        float4 vv = make_float4(0.f, 0.f, 0.f, 0.f);
        if (gi >= 0 && gi < Hc && gj >= 0 && gj < Wc) {
            size_t base = (size_t)(b * HW + gi * Wc + gj) * (3 * C) + head * HD + d0;
            kv = *reinterpret_cast<const float4*>(g_qkv + base + C);
            vv = *reinterpret_cast<const float4*>(g_qkv + base + 2 * C);
        }
        float* kp = ks + pos * 33 + d0;
        float* vp = vs + pos * 33 + d0;
        kp[0] = kv.x; kp[1] = kv.y; kp[2] = kv.z; kp[3] = kv.w;
        vp[0] = vv.x; vp[1] = vv.y; vp[2] = vv.z; vp[3] = vv.w;
    }
    __syncthreads();

    int li = tid >> 3, lj = tid & 7;
    int i = ti * 8 + li;
    int j = tj * 8 + lj;
    int si = min(max(i - 1, 0), Hc - 3);
    int sj = min(max(j - 1, 0), Wc - 3);
    int pi = i - si;
    int pj = j - sj;
    int pbase = (si - r0) * 10 + (sj - c0);

    size_t mq = (size_t)(b * HW + i * Wc + j) * (3 * C) + head * HD;
    float q[HD];
    #pragma unroll
    for (int d = 0; d < HD; d += 4) {
        float4 u = *reinterpret_cast<const float4*>(g_qkv + mq + d);
        q[d] = u.x; q[d + 1] = u.y; q[d + 2] = u.z; q[d + 3] = u.w;
    }

    const float* rp = rpb + head * 25;
    float logits[9];
    #pragma unroll
    for (int a = 0; a < 3; a++)
        #pragma unroll
        for (int c = 0; c < 3; c++) {
            const float* kk = ks + (pbase + a * 10 + c) * 33;
            float s = 0.f;
            #pragma unroll
            for (int d = 0; d < HD; d++) s += q[d] * kk[d];
            logits[a * 3 + c] = s + rp[(a - pi + 2) * 5 + (c - pj + 2)];
        }

    float mx = logits[0];
    #pragma unroll
    for (int n = 1; n < 9; n++) mx = fmaxf(mx, logits[n]);
    float wsum = 0.f;
    float wgt[9];
    #pragma unroll
    for (int n = 0; n < 9; n++) { wgt[n] = expf(logits[n] - mx); wsum += wgt[n]; }
    float inv = 1.0f / wsum;

    float o[HD];
    #pragma unroll
    for (int d = 0; d < HD; d++) o[d] = 0.f;
    #pragma unroll
    for (int n = 0; n < 9; n++) {
        float wn = wgt[n] * inv;
        const float* vv = vs + (pbase + (n / 3) * 10 + (n % 3)) * 33;
        #pragma unroll
        for (int d = 0; d < HD; d++) o[d] += wn * vv[d];
    }

    size_t mo = (size_t)(b * HW + i * Wc + j) * C + head * HD;
    #pragma unroll
    for (int d = 0; d < HD; d += 4) {
        *reinterpret_cast<float4*>(g_attn + mo + d) = make_float4(o[d], o[d + 1], o[d + 2], o[d + 3]);
    }
}

// ---------------------------------------------------------------------------
// Launch
// ---------------------------------------------------------------------------
extern "C" void kernel_launch(void* const* d_in, const int* in_sizes, int n_in,
                              void* d_out, int out_size) {
    const float* xq      = (const float*)d_in[0];
    const float* xkv     = (const float*)d_in[1];
    const float* conv1_w = (const float*)d_in[2];
    const float* conv1_b = (const float*)d_in[3];
    const float* conv3_w = (const float*)d_in[4];
    const float* conv3_b = (const float*)d_in[5];
    const float* ln1_w   = (const float*)d_in[6];
    const float* ln1_b   = (const float*)d_in[7];
    const float* ln10_w  = (const float*)d_in[8];
    const float* ln10_b  = (const float*)d_in[9];
    const float* ln3_w   = (const float*)d_in[10];
    const float* ln3_b   = (const float*)d_in[11];
    const float* wq      = (const float*)d_in[12];
    const float* bq      = (const float*)d_in[13];
    const float* wkv     = (const float*)d_in[14];
    const float* bkv     = (const float*)d_in[15];
    const float* rpb     = (const float*)d_in[16];
    const float* wp      = (const float*)d_in[17];
    const float* bp      = (const float*)d_in[18];
    const float* fc1_w   = (const float*)d_in[19];
    const float* fc1_b   = (const float*)d_in[20];
    const float* fc2_w   = (const float*)d_in[21];
    const float* fc2_b   = (const float*)d_in[22];
    float* out = (float*)d_out;

    float *p_x1, *p_x3, *p_qkv, *p_attn, *p_att, *p_mlp,
          *p_st1, *p_st3, *p_wt1, *p_wt3, *p_wqkv, *p_bqkv, *p_wfc1, *p_bfc1;
    cudaGetSymbolAddress((void**)&p_x1, g_x1);
    cudaGetSymbolAddress((void**)&p_x3, g_x3);
    cudaGetSymbolAddress((void**)&p_qkv, g_qkv);
    cudaGetSymbolAddress((void**)&p_attn, g_attn);
    cudaGetSymbolAddress((void**)&p_att, g_att);
    cudaGetSymbolAddress((void**)&p_mlp, g_mlp);
    cudaGetSymbolAddress((void**)&p_st1, g_stats1);
    cudaGetSymbolAddress((void**)&p_st3, g_stats3);
    cudaGetSymbolAddress((void**)&p_wt1, g_wt1);
    cudaGetSymbolAddress((void**)&p_wt3, g_wt3);
    cudaGetSymbolAddress((void**)&p_wqkv, g_wqkv);
    cudaGetSymbolAddress((void**)&p_bqkv, g_bqkv);
    cudaGetSymbolAddress((void**)&p_wfc1, g_wfc1);
    cudaGetSymbolAddress((void**)&p_bfc1, g_bfc1);

    // allow >48KB dynamic smem on the GEMM instantiations (idempotent)
    cudaFuncSetAttribute(gemm_tc<1,0,KC,C>,      cudaFuncAttributeMaxDynamicSharedMemorySize, SMEM_BYTES);
    cudaFuncSetAttribute(gemm_tc<2,0,C,3*C>,     cudaFuncAttributeMaxDynamicSharedMemorySize, SMEM_BYTES);
    cudaFuncSetAttribute(gemm_tc<0,1,C,C>,       cudaFuncAttributeMaxDynamicSharedMemorySize, SMEM_BYTES);
    cudaFuncSetAttribute(gemm_tc<2,2,C,2*C>,     cudaFuncAttributeMaxDynamicSharedMemorySize, SMEM_BYTES);
    cudaFuncSetAttribute(gemm_tc<0,3,2*C,C>,     cudaFuncAttributeMaxDynamicSharedMemorySize, SMEM_BYTES);

    // 1. weight preprocessing
    transpose_convw<<<(KC * C + 255) / 256, 256>>>(conv1_w, p_wt1);
    transpose_convw<<<(KC * C + 255) / 256, 256>>>(conv3_w, p_wt3);
    fold_qkv<<<3 * C, 256>>>(wq, bq, wkv, bkv, ln1_w, ln1_b, ln10_w, ln10_b);
    fold_fc1<<<2 * C, 256>>>(fc1_w, fc1_b, ln3_w, ln3_b);

    // 2. convs (implicit im2col, tensor cores)
    gemm_tc<1,0,KC,C><<<dim3(M / BM, C / BN), 256, SMEM_BYTES>>>(
        xq, p_wt1, conv1_b, nullptr, nullptr, p_x1);
    gemm_tc<1,0,KC,C><<<dim3(M / BM, C / BN), 256, SMEM_BYTES>>>(
        xkv, p_wt3, conv3_b, nullptr, nullptr, p_x3);

    // 3. LN stats for x1
    ln_stats<<<M / 8, 256>>>(p_x1, p_st1);

    // 4. fused LN + qkv projection
    gemm_tc<2,0,C,3*C><<<dim3(M / BM, (3 * C) / BN), 256, SMEM_BYTES>>>(
        p_x1, p_wqkv, p_bqkv, p_st1, nullptr, p_qkv);

    // 5. neighborhood attention
    nat_attn<<<dim3(14 * 14, HEADS, Bn), 64>>>(rpb);

    // 6. output projection + x3 residual
    gemm_tc<0,1,C,C><<<dim3(M / BM, C / BN), 256, SMEM_BYTES>>>(
        p_attn, wp, bp, nullptr, p_x3, p_att);

    // 7. LN stats for att
    ln_stats<<<M / 8, 256>>>(p_att, p_st3);

    // 8. fused LN + fc1 + GELU
    gemm_tc<2,2,C,2*C><<<dim3(M / BM, (2 * C) / BN), 256, SMEM_BYTES>>>(
        p_att, p_wfc1, p_bfc1, p_st3, nullptr, p_mlp);

    // 9. fc2 + att residual, NCHW transposed store
    gemm_tc<0,3,2*C,C><<<dim3(M / BM, C / BN), 256, SMEM_BYTES>>>(
        p_mlp, fc2_w, fc2_b, nullptr, p_att, out);
}

// round 3
// speedup vs baseline: 2.1520x; 1.0016x over previous
#include <cuda_runtime.h>
#include <math.h>
#include <stdint.h>

// ---------------------------------------------------------------------------
// NAT Global Transformer block. Round 2: all GEMMs on tf32 tensor cores.
// B=2, IMG=112, CIN=64, C=256, HEADS=8, HD=32, K=3
// ---------------------------------------------------------------------------

constexpr int Bn    = 2;
constexpr int Hc    = 112;
constexpr int Wc    = 112;
constexpr int CIN   = 64;
constexpr int C     = 256;
constexpr int HEADS = 8;
constexpr int HD    = 32;
constexpr int HW    = Hc * Wc;        // 12544
constexpr int M     = Bn * HW;        // 25088
constexpr int KC    = CIN * 9;        // 576  (im2col K)

// ---------------- scratch (static device arrays; no allocation) ------------
__device__ float g_x1[M * C];                 // conv1 out, NHWC
__device__ float g_x3[M * C];                 // conv3 out, NHWC
__device__ float g_qkv[M * 3 * C];            // [m][q|k|v] (768 cols)
__device__ float g_attn[M * C];               // attention out (pre-proj)
__device__ float g_att[M * C];                // proj + x3 residual
__device__ float g_mlp[M * 2 * C];            // gelu(fc1)
__device__ float g_stats1[M * 2];             // mean,rstd of x1
__device__ float g_stats3[M * 2];             // mean,rstd of att
__device__ float g_wt1[KC * C];               // conv1 weights, [k][co]
__device__ float g_wt3[KC * C];
__device__ float g_wqkv[C * 3 * C];           // LN-folded [wq*scale | wkv]
__device__ float g_bqkv[3 * C];
__device__ float g_wfc1[C * 2 * C];           // LN3-folded fc1
__device__ float g_bfc1[2 * C];

// ---------------------------------------------------------------------------
// Weight preprocessing
// ---------------------------------------------------------------------------
__global__ void transpose_convw(const float* __restrict__ w, float* __restrict__ wt) {
    int idx = blockIdx.x * 256 + threadIdx.x;      // KC*C = 147456
    if (idx < KC * C) {
        int k = idx / C, co = idx % C;
        wt[idx] = w[co * KC + k];                  // OIHW -> [k][co]
    }
}

__global__ void fold_qkv(const float* __restrict__ wq, const float* __restrict__ bq,
                         const float* __restrict__ wkv, const float* __restrict__ bkv,
                         const float* __restrict__ w1, const float* __restrict__ b1,
                         const float* __restrict__ w10, const float* __restrict__ b10) {
    __shared__ float red[256];
    int n = blockIdx.x;          // 0..767
    int i = threadIdx.x;         // 0..255
    float scale = 1.0f / sqrtf((float)HD);
    float we, bc;
    if (n < C) {
        float w = wq[i * C + n];
        we = w1[i] * w * scale;
        bc = b1[i] * w;
    } else {
        int j = n - C;
        float w = wkv[i * (2 * C) + j];
        we = w10[i] * w;
        bc = b10[i] * w;
    }
    g_wqkv[i * (3 * C) + n] = we;
    red[i] = bc;
    __syncthreads();
    for (int s = 128; s > 0; s >>= 1) {
        if (i < s) red[i] += red[i + s];
        __syncthreads();
    }
    if (i == 0) {
        if (n < C) g_bqkv[n] = (red[0] + bq[n]) * scale;
        else       g_bqkv[n] = red[0] + bkv[n - C];
    }
}

__global__ void fold_fc1(const float* __restrict__ fc1_w, const float* __restrict__ fc1_b,
                         const float* __restrict__ w3, const float* __restrict__ b3) {
    __shared__ float red[256];
    int n = blockIdx.x;          // 0..511
    int i = threadIdx.x;         // 0..255
    float w = fc1_w[i * (2 * C) + n];
    g_wfc1[i * (2 * C) + n] = w3[i] * w;
    red[i] = b3[i] * w;
    __syncthreads();
    for (int s = 128; s > 0; s >>= 1) {
        if (i < s) red[i] += red[i + s];
        __syncthreads();
    }
    if (i == 0) g_bfc1[n] = red[0] + fc1_b[n];
}

// ---------------------------------------------------------------------------
// LayerNorm stats
// ---------------------------------------------------------------------------
__global__ void ln_stats(const float* __restrict__ x, float* __restrict__ stats) {
    int m = blockIdx.x * 8 + (threadIdx.x >> 5);
    int lane = threadIdx.x & 31;
    const float4* p = reinterpret_cast<const float4*>(x + (size_t)m * C);
    float4 u0 = p[lane];
    float4 u1 = p[lane + 32];
    float s  = u0.x + u0.y + u0.z + u0.w + u1.x + u1.y + u1.z + u1.w;
    float ss = u0.x*u0.x + u0.y*u0.y + u0.z*u0.z + u0.w*u0.w
             + u1.x*u1.x + u1.y*u1.y + u1.z*u1.z + u1.w*u1.w;
    #pragma unroll
    for (int o = 16; o > 0; o >>= 1) {
        s  += __shfl_xor_sync(0xFFFFFFFFu, s, o);
        ss += __shfl_xor_sync(0xFFFFFFFFu, ss, o);
    }
    if (lane == 0) {
        float mu  = s * (1.0f / C);
        float var = ss * (1.0f / C) - mu * mu;
        stats[2 * m]     = mu;
        stats[2 * m + 1] = rsqrtf(var + 1e-5f);
    }
}

// ---------------------------------------------------------------------------
// tf32 tensor-core GEMM: 128x64x32 block tile, 8 warps, m16n8k8 mma.
// ALOADER: 0 plain, 1 implicit im2col (NCHW input), 2 LN-normalized
// EPI:     0 +bias | 1 +bias+res | 2 +bias,GELU | 3 +bias+res, NCHW store
// ---------------------------------------------------------------------------
__device__ __forceinline__ float gelu_exact(float x) {
    return 0.5f * x * (1.0f + erff(x * 0.70710678118654752440f));
}
__device__ __forceinline__ float f2tf(float x) {
    uint32_t r;
    asm("cvt.rna.tf32.f32 %0, %1;" : "=r"(r) : "f"(x));
    return __uint_as_float(r);
}
__device__ __forceinline__ void ldsm4(uint32_t addr, uint32_t& r0, uint32_t& r1,
                                      uint32_t& r2, uint32_t& r3) {
    asm volatile("ldmatrix.sync.aligned.m8n8.x4.shared.b16 {%0,%1,%2,%3}, [%4];"
                 : "=r"(r0), "=r"(r1), "=r"(r2), "=r"(r3) : "r"(addr));
}
__device__ __forceinline__ void mma_tf32(float c[4], uint32_t a0, uint32_t a1,
                                         uint32_t a2, uint32_t a3,
                                         uint32_t b0, uint32_t b1) {
    asm volatile(
        "mma.sync.aligned.m16n8k8.row.col.f32.tf32.tf32.f32 "
        "{%0,%1,%2,%3}, {%4,%5,%6,%7}, {%8,%9}, {%0,%1,%2,%3};"
        : "+f"(c[0]), "+f"(c[1]), "+f"(c[2]), "+f"(c[3])
        : "r"(a0), "r"(a1), "r"(a2), "r"(a3), "r"(b0), "r"(b1));
}

constexpr int BM = 128, BN = 64, BK = 32;
constexpr int APAD = 4;                      // row stride 36 floats
constexpr int AST = BK + APAD;               // 36
constexpr int BST = BK + APAD;               // 36
constexpr int ASZ = BM * AST;                // floats
constexpr int BSZ = BN * BST;
constexpr int SMEM_BYTES = 2 * (ASZ + BSZ) * 4;   // 55296

template <int ALOADER, int EPI, int KDIM, int NDIM>
__global__ void __launch_bounds__(256, 2)
gemm_tc(const float* __restrict__ A, const float* __restrict__ Bm,
        const float* __restrict__ bias, const float* __restrict__ stats,
        const float* __restrict__ res, float* __restrict__ out) {
    extern __shared__ float smem[];

    int tid  = threadIdx.x;
    int lane = tid & 31;
    int warp = tid >> 5;
    int bm = blockIdx.x * BM;
    int bn = blockIdx.y * BN;
    int wm = (warp & 3) * 32;        // warp m offset in tile
    int wn = (warp >> 2) * 32;       // warp n offset in tile

    // producer mappings
    int a_m  = tid >> 1;             // 0..127
    int a_kq = (tid & 1) * 16;       // 0 or 16
    int gm   = bm + a_m;
    int b_n  = tid & 63;
    int b_k8 = (tid >> 6) * 8;       // 0,8,16,24

    int bb = 0, hh = 0, ww = 0;
    if (ALOADER == 1) {
        bb = gm / HW;
        int r = gm - bb * HW;
        hh = r / Wc;
        ww = r - hh * Wc;
    }
    float mu = 0.f, rs = 1.f;
    if (ALOADER == 2) {
        mu = stats[2 * gm];
        rs = stats[2 * gm + 1];
    }

    // smem fragment addresses (per buffer, ldmatrix lane addressing)
    uint32_t smem_u = (uint32_t)__cvta_generic_to_shared(smem);
    int arow = wm + (lane & 7) + ((lane >> 3) & 1) * 8;
    int acol = ((lane >> 4) & 1) * 4;
    int brow = wn + ((lane >> 4) & 1) * 8 + (lane & 7);
    int bcol = ((lane >> 3) & 1) * 4;

    uint32_t aAddr[2][2], bAddr[2][2];     // [buf][mt / p]
    #pragma unroll
    for (int buf = 0; buf < 2; buf++) {
        uint32_t base = smem_u + buf * (ASZ + BSZ) * 4;
        #pragma unroll
        for (int mt = 0; mt < 2; mt++)
            aAddr[buf][mt] = base + ((arow + mt * 16) * AST + acol) * 4;
        #pragma unroll
        for (int p = 0; p < 2; p++)
            bAddr[buf][p] = base + ASZ * 4 + ((brow + p * 16) * BST + bcol) * 4;
    }

    float acc[2][4][4];
    #pragma unroll
    for (int mt = 0; mt < 2; mt++)
        #pragma unroll
        for (int nt = 0; nt < 4; nt++)
            #pragma unroll
            for (int r = 0; r < 4; r++) acc[mt][nt][r] = 0.f;

    float ra[16], rb[8];

    auto load_gmem = [&](int k0) {
        if (ALOADER == 1) {
            #pragma unroll
            for (int i = 0; i < 16; i++) {
                int k = k0 + a_kq + i;
                int cin = k / 9;
                int t   = k - cin * 9;
                int rr = hh + t / 3 - 1;
                int cc = ww + t % 3 - 1;
                ra[i] = (rr >= 0 && rr < Hc && cc >= 0 && cc < Wc)
                        ? A[((size_t)(bb * CIN + cin) * Hc + rr) * Wc + cc] : 0.f;
            }
        } else {
            const float4* ap = reinterpret_cast<const float4*>(A + (size_t)gm * KDIM + k0 + a_kq);
            #pragma unroll
            for (int v = 0; v < 4; v++) {
                float4 u = ap[v];
                ra[v*4+0] = u.x; ra[v*4+1] = u.y; ra[v*4+2] = u.z; ra[v*4+3] = u.w;
            }
            if (ALOADER == 2) {
                #pragma unroll
                for (int i = 0; i < 16; i++) ra[i] = (ra[i] - mu) * rs;
            }
        }
        #pragma unroll
        for (int j = 0; j < 8; j++)
            rb[j] = Bm[(size_t)(k0 + b_k8 + j) * NDIM + bn + b_n];
    };

    auto store_smem = [&](int buf) {
        float* As = smem + buf * (ASZ + BSZ);
        float* Bs = As + ASZ;
        float4* ad = reinterpret_cast<float4*>(&As[a_m * AST + a_kq]);
        #pragma unroll
        for (int v = 0; v < 4; v++)
            ad[v] = make_float4(f2tf(ra[v*4+0]), f2tf(ra[v*4+1]),
                                f2tf(ra[v*4+2]), f2tf(ra[v*4+3]));
        float4* bd = reinterpret_cast<float4*>(&Bs[b_n * BST + b_k8]);
        bd[0] = make_float4(f2tf(rb[0]), f2tf(rb[1]), f2tf(rb[2]), f2tf(rb[3]));
        bd[1] = make_float4(f2tf(rb[4]), f2tf(rb[5]), f2tf(rb[6]), f2tf(rb[7]));
    };

    auto compute = [&](int buf) {
        #pragma unroll
        for (int ks = 0; ks < 4; ks++) {
            uint32_t a[2][4], b[2][4];
            #pragma unroll
            for (int mt = 0; mt < 2; mt++)
                ldsm4(aAddr[buf][mt] + ks * 32, a[mt][0], a[mt][1], a[mt][2], a[mt][3]);
            #pragma unroll
            for (int p = 0; p < 2; p++)
                ldsm4(bAddr[buf][p] + ks * 32, b[p][0], b[p][1], b[p][2], b[p][3]);
            #pragma unroll
            for (int mt = 0; mt < 2; mt++)
                #pragma unroll
                for (int p = 0; p < 2; p++) {
                    mma_tf32(acc[mt][2*p],   a[mt][0], a[mt][1], a[mt][2], a[mt][3],
                             b[p][0], b[p][1]);
                    mma_tf32(acc[mt][2*p+1], a[mt][0], a[mt][1], a[mt][2], a[mt][3],
                             b[p][2], b[p][3]);
                }
        }
    };

    constexpr int NIT = KDIM / BK;
    load_gmem(0);
    store_smem(0);
    __syncthreads();
    for (int it = 0; it < NIT; ++it) {
        if (it + 1 < NIT) load_gmem((it + 1) * BK);
        compute(it & 1);
        if (it + 1 < NIT) store_smem((it + 1) & 1);
        __syncthreads();
    }

    // epilogue
    int row0 = lane >> 2;
    int col0 = (lane & 3) * 2;
    #pragma unroll
    for (int mt = 0; mt < 2; mt++) {
        #pragma unroll
        for (int half = 0; half < 2; half++) {
            int m = bm + wm + mt * 16 + row0 + half * 8;
            int mb = m / HW;
            int mp = m - mb * HW;
            #pragma unroll
            for (int nt = 0; nt < 4; nt++) {
                int n = bn + wn + nt * 8 + col0;
                float v0 = acc[mt][nt][half * 2 + 0];
                float v1 = acc[mt][nt][half * 2 + 1];
                float2 bi = *reinterpret_cast<const float2*>(&bias[n]);
                v0 += bi.x; v1 += bi.y;
                if constexpr (EPI == 1 || EPI == 3) {
                    float2 rr = *reinterpret_cast<const float2*>(&res[(size_t)m * NDIM + n]);
                    v0 += rr.x; v1 += rr.y;
                }
                if constexpr (EPI == 2) { v0 = gelu_exact(v0); v1 = gelu_exact(v1); }
                if constexpr (EPI == 3) {
                    out[((size_t)mb * C + n) * HW + mp]     = v0;
                    out[((size_t)mb * C + n + 1) * HW + mp] = v1;
                } else {
                    *reinterpret_cast<float2*>(&out[(size_t)m * NDIM + n]) = make_float2(v0, v1);
                }
            }
        }
    }
}

// ---------------------------------------------------------------------------
// 3x3 neighborhood attention (unchanged from round 1)
// ---------------------------------------------------------------------------
__global__ void __launch_bounds__(64)
nat_attn(const float* __restrict__ rpb) {
    __shared__ float ks[100 * 33];
    __shared__ float vs[100 * 33];

    int ti = blockIdx.x / 14;
    int tj = blockIdx.x % 14;
    int head = blockIdx.y;
    int b = blockIdx.z;
    int tid = threadIdx.x;

    int r0 = ti * 8 - 1;
    int c0 = tj * 8 - 1;

    for (int idx = tid; idx < 100 * 8; idx += 64) {
        int pos = idx >> 3;
        int d0  = (idx & 7) * 4;
        int rr = pos / 10, cc = pos % 10;
        int gi = r0 + rr, gj = c0 + cc;
        float4 kv = make_float4(0.f, 0.f, 0.f, 0.f);
        float4 vv = make_float4(0.f, 0.f, 0.f, 0.f);
        if (gi >= 0 && gi < Hc && gj >= 0 && gj < Wc) {
            size_t base = (size_t)(b * HW + gi * Wc + gj) * (3 * C) + head * HD + d0;
            kv = *reinterpret_cast<const float4*>(g_qkv + base + C);
            vv = *reinterpret_cast<const float4*>(g_qkv + base + 2 * C);
        }
        float* kp = ks + pos * 33 + d0;
        float* vp = vs + pos * 33 + d0;
        kp[0] = kv.x; kp[1] = kv.y; kp[2] = kv.z; kp[3] = kv.w;
        vp[0] = vv.x; vp[1] = vv.y; vp[2] = vv.z; vp[3] = vv.w;
    }
    __syncthreads();

    int li = tid >> 3, lj = tid & 7;
    int i = ti * 8 + li;
    int j = tj * 8 + lj;
    int si = min(max(i - 1, 0), Hc - 3);
    int sj = min(max(j - 1, 0), Wc - 3);
    int pi = i - si;
    int pj = j - sj;
    int pbase = (si - r0) * 10 + (sj - c0);

    size_t mq = (size_t)(b * HW + i * Wc + j) * (3 * C) + head * HD;
    float q[HD];
    #pragma unroll
    for (int d = 0; d < HD; d += 4) {
        float4 u = *reinterpret_cast<const float4*>(g_qkv + mq + d);
        q[d] = u.x; q[d + 1] = u.y; q[d + 2] = u.z; q[d + 3] = u.w;
    }

    const float* rp = rpb + head * 25;
    float logits[9];
    #pragma unroll
    for (int a = 0; a < 3; a++)
        #pragma unroll
        for (int c = 0; c < 3; c++) {
            const float* kk = ks + (pbase + a * 10 + c) * 33;
            float s = 0.f;
            #pragma unroll
            for (int d = 0; d < HD; d++) s += q[d] * kk[d];
            logits[a * 3 + c] = s + rp[(a - pi + 2) * 5 + (c - pj + 2)];
        }

    float mx = logits[0];
    #pragma unroll
    for (int n = 1; n < 9; n++) mx = fmaxf(mx, logits[n]);
    float wsum = 0.f;
    float wgt[9];
    #pragma unroll
    for (int n = 0; n < 9; n++) { wgt[n] = expf(logits[n] - mx); wsum += wgt[n]; }
    float inv = 1.0f / wsum;

    float o[HD];
    #pragma unroll
    for (int d = 0; d < HD; d++) o[d] = 0.f;
    #pragma unroll
    for (int n = 0; n < 9; n++) {
        float wn = wgt[n] * inv;
        const float* vv = vs + (pbase + (n / 3) * 10 + (n % 3)) * 33;
        #pragma unroll
        for (int d = 0; d < HD; d++) o[d] += wn * vv[d];
    }

    size_t mo = (size_t)(b * HW + i * Wc + j) * C + head * HD;
    #pragma unroll
    for (int d = 0; d < HD; d += 4) {
        *reinterpret_cast<float4*>(g_attn + mo + d) = make_float4(o[d], o[d + 1], o[d + 2], o[d + 3]);
    }
}

// ---------------------------------------------------------------------------
// Launch
// ---------------------------------------------------------------------------
extern "C" void kernel_launch(void* const* d_in, const int* in_sizes, int n_in,
                              void* d_out, int out_size) {
    const float* xq      = (const float*)d_in[0];
    const float* xkv     = (const float*)d_in[1];
    const float* conv1_w = (const float*)d_in[2];
    const float* conv1_b = (const float*)d_in[3];
    const float* conv3_w = (const float*)d_in[4];
    const float* conv3_b = (const float*)d_in[5];
    const float* ln1_w   = (const float*)d_in[6];
    const float* ln1_b   = (const float*)d_in[7];
    const float* ln10_w  = (const float*)d_in[8];
    const float* ln10_b  = (const float*)d_in[9];
    const float* ln3_w   = (const float*)d_in[10];
    const float* ln3_b   = (const float*)d_in[11];
    const float* wq      = (const float*)d_in[12];
    const float* bq      = (const float*)d_in[13];
    const float* wkv     = (const float*)d_in[14];
    const float* bkv     = (const float*)d_in[15];
    const float* rpb     = (const float*)d_in[16];
    const float* wp      = (const float*)d_in[17];
    const float* bp      = (const float*)d_in[18];
    const float* fc1_w   = (const float*)d_in[19];
    const float* fc1_b   = (const float*)d_in[20];
    const float* fc2_w   = (const float*)d_in[21];
    const float* fc2_b   = (const float*)d_in[22];
    float* out = (float*)d_out;

    float *p_x1, *p_x3, *p_qkv, *p_attn, *p_att, *p_mlp,
          *p_st1, *p_st3, *p_wt1, *p_wt3, *p_wqkv, *p_bqkv, *p_wfc1, *p_bfc1;
    cudaGetSymbolAddress((void**)&p_x1, g_x1);
    cudaGetSymbolAddress((void**)&p_x3, g_x3);
    cudaGetSymbolAddress((void**)&p_qkv, g_qkv);
    cudaGetSymbolAddress((void**)&p_attn, g_attn);
    cudaGetSymbolAddress((void**)&p_att, g_att);
    cudaGetSymbolAddress((void**)&p_mlp, g_mlp);
    cudaGetSymbolAddress((void**)&p_st1, g_stats1);
    cudaGetSymbolAddress((void**)&p_st3, g_stats3);
    cudaGetSymbolAddress((void**)&p_wt1, g_wt1);
    cudaGetSymbolAddress((void**)&p_wt3, g_wt3);
    cudaGetSymbolAddress((void**)&p_wqkv, g_wqkv);
    cudaGetSymbolAddress((void**)&p_bqkv, g_bqkv);
    cudaGetSymbolAddress((void**)&p_wfc1, g_wfc1);
    cudaGetSymbolAddress((void**)&p_bfc1, g_bfc1);

    // allow >48KB dynamic smem on the GEMM instantiations (idempotent)
    cudaFuncSetAttribute(gemm_tc<1,0,KC,C>,      cudaFuncAttributeMaxDynamicSharedMemorySize, SMEM_BYTES);
    cudaFuncSetAttribute(gemm_tc<2,0,C,3*C>,     cudaFuncAttributeMaxDynamicSharedMemorySize, SMEM_BYTES);
    cudaFuncSetAttribute(gemm_tc<0,1,C,C>,       cudaFuncAttributeMaxDynamicSharedMemorySize, SMEM_BYTES);
    cudaFuncSetAttribute(gemm_tc<2,2,C,2*C>,     cudaFuncAttributeMaxDynamicSharedMemorySize, SMEM_BYTES);
    cudaFuncSetAttribute(gemm_tc<0,3,2*C,C>,     cudaFuncAttributeMaxDynamicSharedMemorySize, SMEM_BYTES);

    // 1. weight preprocessing
    transpose_convw<<<(KC * C + 255) / 256, 256>>>(conv1_w, p_wt1);
    transpose_convw<<<(KC * C + 255) / 256, 256>>>(conv3_w, p_wt3);
    fold_qkv<<<3 * C, 256>>>(wq, bq, wkv, bkv, ln1_w, ln1_b, ln10_w, ln10_b);
    fold_fc1<<<2 * C, 256>>>(fc1_w, fc1_b, ln3_w, ln3_b);

    // 2. convs (implicit im2col, tensor cores)
    gemm_tc<1,0,KC,C><<<dim3(M / BM, C / BN), 256, SMEM_BYTES>>>(
        xq, p_wt1, conv1_b, nullptr, nullptr, p_x1);
    gemm_tc<1,0,KC,C><<<dim3(M / BM, C / BN), 256, SMEM_BYTES>>>(
        xkv, p_wt3, conv3_b, nullptr, nullptr, p_x3);

    // 3. LN stats for x1
    ln_stats<<<M / 8, 256>>>(p_x1, p_st1);

    // 4. fused LN + qkv projection
    gemm_tc<2,0,C,3*C><<<dim3(M / BM, (3 * C) / BN), 256, SMEM_BYTES>>>(
        p_x1, p_wqkv, p_bqkv, p_st1, nullptr, p_qkv);

    // 5. neighborhood attention
    nat_attn<<<dim3(14 * 14, HEADS, Bn), 64>>>(rpb);

    // 6. output projection + x3 residual
    gemm_tc<0,1,C,C><<<dim3(M / BM, C / BN), 256, SMEM_BYTES>>>(
        p_attn, wp, bp, nullptr, p_x3, p_att);

    // 7. LN stats for att
    ln_stats<<<M / 8, 256>>>(p_att, p_st3);

    // 8. fused LN + fc1 + GELU
    gemm_tc<2,2,C,2*C><<<dim3(M / BM, (2 * C) / BN), 256, SMEM_BYTES>>>(
        p_att, p_wfc1, p_bfc1, p_st3, nullptr, p_mlp);

    // 9. fc2 + att residual, NCHW transposed store
    gemm_tc<0,3,2*C,C><<<dim3(M / BM, C / BN), 256, SMEM_BYTES>>>(
        p_mlp, fc2_w, fc2_b, nullptr, p_att, out);
}

// round 5
// speedup vs baseline: 2.9780x; 1.3839x over previous
#include <cuda_runtime.h>
#include <math.h>
#include <stdint.h>

constexpr int Bn    = 2;
constexpr int Hc    = 112;
constexpr int Wc    = 112;
constexpr int CIN   = 64;
constexpr int C     = 256;
constexpr int HEADS = 8;
constexpr int HD    = 32;
constexpr int HW    = Hc * Wc;        // 12544
constexpr int M     = Bn * HW;        // 25088
constexpr int KC    = CIN * 9;        // 576

// ---------------- scratch ----------------
__device__ __align__(1024) float g_x1[M * C];
__device__ __align__(1024) float g_x3[M * C];
__device__ __align__(1024) float g_qkv[M * 3 * C];
__device__ __align__(1024) float g_attn[M * C];
__device__ __align__(1024) float g_att[M * C];
__device__ __align__(1024) float g_mlp[M * 2 * C];
__device__ __align__(1024) float g_stats1[M * 2];
__device__ __align__(1024) float g_stats3[M * 2];
__device__ __align__(1024) float g_wt1[C * KC];      // [n][k] rna
__device__ __align__(1024) float g_wt3[C * KC];
__device__ __align__(1024) float g_wqkv[3 * C * C];  // [n][k] rna, LN+scale folded
__device__ __align__(1024) float g_bqkv[3 * C];
__device__ __align__(1024) float g_csq[3 * C];
__device__ __align__(1024) float g_wfc1[2 * C * C];  // [n][k] rna, LN folded
__device__ __align__(1024) float g_bfc1[2 * C];
__device__ __align__(1024) float g_csf[2 * C];
__device__ __align__(1024) float g_wpT[C * C];       // [n][k] rna
__device__ __align__(1024) float g_fc2T[C * 2 * C];  // [n][k] rna

// ---------------- helpers ----------------
__device__ __forceinline__ float f2tf(float x) {
    uint32_t r;
    asm("cvt.rna.tf32.f32 %0, %1;" : "=r"(r) : "f"(x));
    return __uint_as_float(r);
}
__device__ __forceinline__ uint32_t smem_u32(const void* p) {
    return (uint32_t)__cvta_generic_to_shared(p);
}
__device__ __forceinline__ void cp16(uint32_t sdst, const void* gsrc) {
    asm volatile("cp.async.cg.shared.global [%0], [%1], 16;" :: "r"(sdst), "l"(gsrc));
}
__device__ __forceinline__ void cp_commit() { asm volatile("cp.async.commit_group;" ::: "memory"); }
__device__ __forceinline__ void cp_wait0()  { asm volatile("cp.async.wait_group 0;" ::: "memory"); }
__device__ __forceinline__ void cp_wait1()  { asm volatile("cp.async.wait_group 1;" ::: "memory"); }
__device__ __forceinline__ void ldsm4(uint32_t addr, uint32_t& r0, uint32_t& r1,
                                      uint32_t& r2, uint32_t& r3) {
    asm volatile("ldmatrix.sync.aligned.m8n8.x4.shared.b16 {%0,%1,%2,%3}, [%4];"
                 : "=r"(r0), "=r"(r1), "=r"(r2), "=r"(r3) : "r"(addr));
}
__device__ __forceinline__ void cvt_tf(uint32_t& r) {
    asm("cvt.rna.tf32.f32 %0, %0;" : "+r"(r));
}
__device__ __forceinline__ void mma_tf32(float c[4], uint32_t a0, uint32_t a1,
                                         uint32_t a2, uint32_t a3,
                                         uint32_t b0, uint32_t b1) {
    asm volatile(
        "mma.sync.aligned.m16n8k8.row.col.f32.tf32.tf32.f32 "
        "{%0,%1,%2,%3}, {%4,%5,%6,%7}, {%8,%9}, {%0,%1,%2,%3};"
        : "+f"(c[0]), "+f"(c[1]), "+f"(c[2]), "+f"(c[3])
        : "r"(a0), "r"(a1), "r"(a2), "r"(a3), "r"(b0), "r"(b1));
}
__device__ __forceinline__ float gelu_exact(float x) {
    return 0.5f * x * (1.0f + erff(x * 0.70710678118654752440f));
}

// ---------------------------------------------------------------------------
// Fused weight preprocessing (one launch). Block ranges:
//  [0,576)      conv1 rna copy (OIHW is already [n][k])
//  [576,1152)   conv3 rna copy
//  [1152,1408)  wp transpose+rna       -> g_wpT
//  [1408,1920)  fc2 transpose+rna      -> g_fc2T
//  [1920,2688)  fold qkv (LN1/LN10 + q-scale) -> g_wqkv/g_bqkv/g_csq
//  [2688,3200)  fold fc1 (LN3)               -> g_wfc1/g_bfc1/g_csf
// ---------------------------------------------------------------------------
__global__ void prep_all(const float* __restrict__ conv1_w, const float* __restrict__ conv3_w,
                         const float* __restrict__ wp, const float* __restrict__ fc2_w,
                         const float* __restrict__ wq, const float* __restrict__ bq,
                         const float* __restrict__ wkv, const float* __restrict__ bkv,
                         const float* __restrict__ w1, const float* __restrict__ b1,
                         const float* __restrict__ w10, const float* __restrict__ b10,
                         const float* __restrict__ fc1_w, const float* __restrict__ fc1_b,
                         const float* __restrict__ w3, const float* __restrict__ b3) {
    __shared__ float red[256];
    int blk = blockIdx.x;
    int i = threadIdx.x;
    if (blk < 1152) {
        int idx = (blk % 576) * 256 + i;
        if (blk < 576) g_wt1[idx] = f2tf(conv1_w[idx]);
        else           g_wt3[idx] = f2tf(conv3_w[idx]);
        return;
    }
    if (blk < 1408) {
        int idx = (blk - 1152) * 256 + i;        // over C*C
        int n = idx >> 8, k = idx & 255;
        g_wpT[idx] = f2tf(wp[k * C + n]);
        return;
    }
    if (blk < 1920) {
        int idx = (blk - 1408) * 256 + i;        // over C*2C (n-major, K=512)
        int n = idx >> 9, k = idx & 511;
        g_fc2T[idx] = f2tf(fc2_w[k * C + n]);
        return;
    }
    if (blk < 2688) {
        int n = blk - 1920;                      // 0..767
        float scale = 0.17677669529663688f;
        float w, we, bc;
        if (n < C) { w = wq[i * C + n]; we = w1[i] * w * scale; bc = b1[i] * w * scale; }
        else { int j = n - C; w = wkv[i * (2 * C) + j]; we = w10[i] * w; bc = b10[i] * w; }
        float wr = f2tf(we);
        g_wqkv[n * C + i] = wr;
        red[i] = bc; __syncthreads();
        for (int s = 128; s > 0; s >>= 1) { if (i < s) red[i] += red[i + s]; __syncthreads(); }
        if (i == 0) g_bqkv[n] = red[0] + (n < C ? bq[n] * scale : bkv[n - C]);
        __syncthreads();
        red[i] = wr; __syncthreads();
        for (int s = 128; s > 0; s >>= 1) { if (i < s) red[i] += red[i + s]; __syncthreads(); }
        if (i == 0) g_csq[n] = red[0];
        return;
    }
    {
        int n = blk - 2688;                      // 0..511
        float w = fc1_w[i * (2 * C) + n];
        float wr = f2tf(w3[i] * w);
        g_wfc1[n * C + i] = wr;
        red[i] = b3[i] * w; __syncthreads();
        for (int s = 128; s > 0; s >>= 1) { if (i < s) red[i] += red[i + s]; __syncthreads(); }
        if (i == 0) g_bfc1[n] = red[0] + fc1_b[n];
        __syncthreads();
        red[i] = wr; __syncthreads();
        for (int s = 128; s > 0; s >>= 1) { if (i < s) red[i] += red[i + s]; __syncthreads(); }
        if (i == 0) g_csf[n] = red[0];
    }
}

// ---------------- LN stats ----------------
__global__ void ln_stats(const float* __restrict__ x, float* __restrict__ st) {
    int m = blockIdx.x * 8 + (threadIdx.x >> 5);
    int lane = threadIdx.x & 31;
    const float4* p = reinterpret_cast<const float4*>(x + (size_t)m * C);
    float4 u0 = p[lane], u1 = p[lane + 32];
    float s  = u0.x + u0.y + u0.z + u0.w + u1.x + u1.y + u1.z + u1.w;
    float ss = u0.x*u0.x + u0.y*u0.y + u0.z*u0.z + u0.w*u0.w
             + u1.x*u1.x + u1.y*u1.y + u1.z*u1.z + u1.w*u1.w;
    #pragma unroll
    for (int o = 16; o > 0; o >>= 1) {
        s  += __shfl_xor_sync(0xFFFFFFFFu, s, o);
        ss += __shfl_xor_sync(0xFFFFFFFFu, ss, o);
    }
    if (lane == 0) {
        float mu = s * (1.0f / C);
        float var = ss * (1.0f / C) - mu * mu;
        st[2 * m] = mu;
        st[2 * m + 1] = rsqrtf(var + 1e-5f);
    }
}

// ---------------------------------------------------------------------------
// tf32 mma.sync GEMM: 128x128x32 tile, 8 warps (warp tile 64x32),
// cp.async 2-stage pipeline, padded smem (row stride 36 floats).
// B is [n][k] (pre-transposed, rna-rounded). A rounded in consumer.
// ASRC: 0 plain cp.async | 1 implicit im2col (LDG+STS)
// EPI:  0 +bias | 1 +bias+res | 2 LN-affine | 3 LN-affine+GELU | 4 +bias+res NCHW
// ---------------------------------------------------------------------------
constexpr int GBM = 128, GBN = 128, GBK = 32;
constexpr int AST = GBK + 4;                 // 36 floats row stride
constexpr int ASZ = GBM * AST;               // floats
constexpr int BSZ = GBN * AST;
constexpr int STGF = ASZ + BSZ;              // 9216 floats per stage
constexpr int STGB = STGF * 4;               // 36864 bytes
constexpr int DYN_SMEM = 2 * STGB;           // 73728

template <int ASRC, int EPI, int KDIM, int NDIM>
__global__ void __launch_bounds__(256, 2)
gemmk(const float* __restrict__ A, const float* __restrict__ Bw,
      const float* __restrict__ bias, const float* __restrict__ stats,
      const float* __restrict__ csum, const float* __restrict__ res,
      float* __restrict__ out) {
    extern __shared__ float sm[];
    __shared__ float s_bias[GBN];
    __shared__ float s_csum[GBN];

    int tid = threadIdx.x;
    int lane = tid & 31;
    int warp = tid >> 5;
    int bm = blockIdx.x * GBM;
    int bn = blockIdx.y * GBN;
    int wm = (warp & 1) * 64;
    int wn = (warp >> 1) * 32;

    if (tid < GBN) {
        s_bias[tid] = bias[bn + tid];
        if (EPI == 2 || EPI == 3) s_csum[tid] = csum[bn + tid];
    }

    // producer mappings
    int p_row = tid >> 3;            // 0..31 step: +32 rows per sub-iter
    int p_seg = tid & 7;             // 16B chunk within 32-float row
    int a_m = tid >> 1;              // conv path: row 0..127
    int a_kq = (tid & 1) * 16;       // conv path: k half
    int bb = 0, hh = 0, ww = 0;
    if (ASRC == 1) {
        int gm = bm + a_m;
        bb = gm / HW;
        int r = gm - bb * HW;
        hh = r / Wc;
        ww = r - hh * Wc;
    }

    uint32_t sbase = smem_u32(sm);

    auto load_stage = [&](int stg, int k0) {
        uint32_t sA = sbase + stg * STGB;
        uint32_t sB = sA + ASZ * 4;
        if (ASRC == 0) {
            #pragma unroll
            for (int j = 0; j < 4; j++) {
                int row = p_row + j * 32;
                cp16(sA + (row * AST + p_seg * 4) * 4,
                     A + (size_t)(bm + row) * KDIM + k0 + p_seg * 4);
            }
        } else {
            float ra[16];
            #pragma unroll
            for (int i = 0; i < 16; i++) {
                int k = k0 + a_kq + i;
                int cin = k / 9;
                int t = k - cin * 9;
                int rr = hh + t / 3 - 1;
                int cc = ww + t % 3 - 1;
                ra[i] = (rr >= 0 && rr < Hc && cc >= 0 && cc < Wc)
                        ? A[((size_t)(bb * CIN + cin) * Hc + rr) * Wc + cc] : 0.f;
            }
            float* As = sm + stg * STGF;
            float4* ad = reinterpret_cast<float4*>(&As[a_m * AST + a_kq]);
            #pragma unroll
            for (int v = 0; v < 4; v++)
                ad[v] = make_float4(ra[v*4+0], ra[v*4+1], ra[v*4+2], ra[v*4+3]);
        }
        #pragma unroll
        for (int j = 0; j < 4; j++) {
            int row = p_row + j * 32;
            cp16(sB + (row * AST + p_seg * 4) * 4,
                 Bw + (size_t)(bn + row) * KDIM + k0 + p_seg * 4);
        }
    };

    // consumer fragment addresses (buffer 0)
    int arow = wm + (lane & 7) + ((lane >> 3) & 1) * 8;
    int acol = ((lane >> 4) & 1) * 4;
    int brow = wn + ((lane >> 4) & 1) * 8 + (lane & 7);
    int bcol = ((lane >> 3) & 1) * 4;
    uint32_t aA[4], bA[2];
    #pragma unroll
    for (int mt = 0; mt < 4; mt++)
        aA[mt] = sbase + ((arow + mt * 16) * AST + acol) * 4;
    #pragma unroll
    for (int p = 0; p < 2; p++)
        bA[p] = sbase + (ASZ + (brow + p * 16) * AST + bcol) * 4;

    float acc[4][4][4];
    #pragma unroll
    for (int mt = 0; mt < 4; mt++)
        #pragma unroll
        for (int nt = 0; nt < 4; nt++)
            #pragma unroll
            for (int r = 0; r < 4; r++) acc[mt][nt][r] = 0.f;

    auto compute = [&](int buf) {
        uint32_t off = buf * STGB;
        #pragma unroll
        for (int ks = 0; ks < 4; ks++) {
            uint32_t a[4][4], b[2][4];
            #pragma unroll
            for (int mt = 0; mt < 4; mt++) {
                ldsm4(aA[mt] + off + ks * 32, a[mt][0], a[mt][1], a[mt][2], a[mt][3]);
                cvt_tf(a[mt][0]); cvt_tf(a[mt][1]); cvt_tf(a[mt][2]); cvt_tf(a[mt][3]);
            }
            #pragma unroll
            for (int p = 0; p < 2; p++)
                ldsm4(bA[p] + off + ks * 32, b[p][0], b[p][1], b[p][2], b[p][3]);
            #pragma unroll
            for (int mt = 0; mt < 4; mt++)
                #pragma unroll
                for (int p = 0; p < 2; p++) {
                    mma_tf32(acc[mt][2*p],   a[mt][0], a[mt][1], a[mt][2], a[mt][3],
                             b[p][0], b[p][1]);
                    mma_tf32(acc[mt][2*p+1], a[mt][0], a[mt][1], a[mt][2], a[mt][3],
                             b[p][2], b[p][3]);
                }
        }
    };

    constexpr int NIT = KDIM / GBK;
    load_stage(0, 0);
    cp_commit();
    load_stage(1, GBK);
    cp_commit();

    for (int it = 0; it < NIT; ++it) {
        if (it + 1 < NIT) cp_wait1(); else cp_wait0();
        __syncthreads();
        compute(it & 1);
        if (it + 2 < NIT) {
            __syncthreads();
            load_stage(it & 1, (it + 2) * GBK);
            cp_commit();
        }
    }

    // ---------------- epilogue ----------------
    int row0 = lane >> 2;
    int col0 = (lane & 3) * 2;
    #pragma unroll
    for (int mt = 0; mt < 4; mt++) {
        #pragma unroll
        for (int half = 0; half < 2; half++) {
            int m = bm + wm + mt * 16 + row0 + half * 8;
            float rs = 1.f, mu = 0.f;
            if (EPI == 2 || EPI == 3) { mu = stats[2 * m]; rs = stats[2 * m + 1]; }
            int mb = m / HW;
            int mp = m - mb * HW;
            #pragma unroll
            for (int nt = 0; nt < 4; nt++) {
                int nl = wn + nt * 8 + col0;
                int n = bn + nl;
                float v0 = acc[mt][nt][half * 2 + 0];
                float v1 = acc[mt][nt][half * 2 + 1];
                if (EPI == 2 || EPI == 3) {
                    v0 = rs * v0 - rs * mu * s_csum[nl] + s_bias[nl];
                    v1 = rs * v1 - rs * mu * s_csum[nl + 1] + s_bias[nl + 1];
                } else {
                    v0 += s_bias[nl];
                    v1 += s_bias[nl + 1];
                }
                if (EPI == 1 || EPI == 4) {
                    float2 rr = *reinterpret_cast<const float2*>(&res[(size_t)m * NDIM + n]);
                    v0 += rr.x; v1 += rr.y;
                }
                if (EPI == 3) { v0 = gelu_exact(v0); v1 = gelu_exact(v1); }
                if (EPI == 4) {
                    out[((size_t)mb * C + n) * HW + mp]       = v0;
                    out[((size_t)mb * C + n + 1) * HW + mp]   = v1;
                } else {
                    *reinterpret_cast<float2*>(&out[(size_t)m * NDIM + n]) =
                        make_float2(v0, v1);
                }
            }
        }
    }
}

// ---------------- 3x3 neighborhood attention (unchanged) ----------------
__global__ void __launch_bounds__(64)
nat_attn(const float* __restrict__ rpb) {
    __shared__ float ks[100 * 33];
    __shared__ float vs[100 * 33];

    int ti = blockIdx.x / 14;
    int tj = blockIdx.x % 14;
    int head = blockIdx.y;
    int b = blockIdx.z;
    int tid = threadIdx.x;
    int r0 = ti * 8 - 1;
    int c0 = tj * 8 - 1;

    for (int idx = tid; idx < 100 * 8; idx += 64) {
        int pos = idx >> 3;
        int d0 = (idx & 7) * 4;
        int rr = pos / 10, cc = pos % 10;
        int gi = r0 + rr, gj = c0 + cc;
        float4 kv = make_float4(0.f, 0.f, 0.f, 0.f);
        float4 vv = make_float4(0.f, 0.f, 0.f, 0.f);
        if (gi >= 0 && gi < Hc && gj >= 0 && gj < Wc) {
            size_t base = (size_t)(b * HW + gi * Wc + gj) * (3 * C) + head * HD + d0;
            kv = *reinterpret_cast<const float4*>(g_qkv + base + C);
            vv = *reinterpret_cast<const float4*>(g_qkv + base + 2 * C);
        }
        float* kp = ks + pos * 33 + d0;
        float* vp = vs + pos * 33 + d0;
        kp[0] = kv.x; kp[1] = kv.y; kp[2] = kv.z; kp[3] = kv.w;
        vp[0] = vv.x; vp[1] = vv.y; vp[2] = vv.z; vp[3] = vv.w;
    }
    __syncthreads();

    int li = tid >> 3, lj = tid & 7;
    int i = ti * 8 + li;
    int j = tj * 8 + lj;
    int si = min(max(i - 1, 0), Hc - 3);
    int sj = min(max(j - 1, 0), Wc - 3);
    int pi = i - si;
    int pj = j - sj;
    int pbase = (si - r0) * 10 + (sj - c0);

    size_t mq = (size_t)(b * HW + i * Wc + j) * (3 * C) + head * HD;
    float q[HD];
    #pragma unroll
    for (int d = 0; d < HD; d += 4) {
        float4 u = *reinterpret_cast<const float4*>(g_qkv + mq + d);
        q[d] = u.x; q[d+1] = u.y; q[d+2] = u.z; q[d+3] = u.w;
    }

    const float* rp = rpb + head * 25;
    float logits[9];
    #pragma unroll
    for (int a = 0; a < 3; a++)
        #pragma unroll
        for (int c = 0; c < 3; c++) {
            const float* kk = ks + (pbase + a * 10 + c) * 33;
            float s = 0.f;
            #pragma unroll
            for (int d = 0; d < HD; d++) s += q[d] * kk[d];
            logits[a * 3 + c] = s + rp[(a - pi + 2) * 5 + (c - pj + 2)];
        }

    float mx = logits[0];
    #pragma unroll
    for (int n = 1; n < 9; n++) mx = fmaxf(mx, logits[n]);
    float wsum = 0.f, wgt[9];
    #pragma unroll
    for (int n = 0; n < 9; n++) { wgt[n] = expf(logits[n] - mx); wsum += wgt[n]; }
    float inv = 1.0f / wsum;

    float o[HD];
    #pragma unroll
    for (int d = 0; d < HD; d++) o[d] = 0.f;
    #pragma unroll
    for (int n = 0; n < 9; n++) {
        float wn = wgt[n] * inv;
        const float* vv = vs + (pbase + (n / 3) * 10 + (n % 3)) * 33;
        #pragma unroll
        for (int d = 0; d < HD; d++) o[d] += wn * vv[d];
    }

    size_t mo = (size_t)(b * HW + i * Wc + j) * C + head * HD;
    #pragma unroll
    for (int d = 0; d < HD; d += 4)
        *reinterpret_cast<float4*>(g_attn + mo + d) = make_float4(o[d], o[d+1], o[d+2], o[d+3]);
}

// ---------------- launch ----------------
extern "C" void kernel_launch(void* const* d_in, const int* in_sizes, int n_in,
                              void* d_out, int out_size) {
    const float* xq      = (const float*)d_in[0];
    const float* xkv     = (const float*)d_in[1];
    const float* conv1_w = (const float*)d_in[2];
    const float* conv1_b = (const float*)d_in[3];
    const float* conv3_w = (const float*)d_in[4];
    const float* conv3_b = (const float*)d_in[5];
    const float* ln1_w   = (const float*)d_in[6];
    const float* ln1_b   = (const float*)d_in[7];
    const float* ln10_w  = (const float*)d_in[8];
    const float* ln10_b  = (const float*)d_in[9];
    const float* ln3_w   = (const float*)d_in[10];
    const float* ln3_b   = (const float*)d_in[11];
    const float* wq      = (const float*)d_in[12];
    const float* bq      = (const float*)d_in[13];
    const float* wkv     = (const float*)d_in[14];
    const float* bkv     = (const float*)d_in[15];
    const float* rpb     = (const float*)d_in[16];
    const float* wp      = (const float*)d_in[17];
    const float* bp      = (const float*)d_in[18];
    const float* fc1_w   = (const float*)d_in[19];
    const float* fc1_b   = (const float*)d_in[20];
    const float* fc2_w   = (const float*)d_in[21];
    const float* fc2_b   = (const float*)d_in[22];
    float* out = (float*)d_out;

    float *p_x1, *p_x3, *p_qkv, *p_attn, *p_att, *p_mlp, *p_st1, *p_st3,
          *p_wt1, *p_wt3, *p_wqkv, *p_bqkv, *p_csq, *p_wfc1, *p_bfc1, *p_csf,
          *p_wpT, *p_fc2T;
    cudaGetSymbolAddress((void**)&p_x1, g_x1);
    cudaGetSymbolAddress((void**)&p_x3, g_x3);
    cudaGetSymbolAddress((void**)&p_qkv, g_qkv);
    cudaGetSymbolAddress((void**)&p_attn, g_attn);
    cudaGetSymbolAddress((void**)&p_att, g_att);
    cudaGetSymbolAddress((void**)&p_mlp, g_mlp);
    cudaGetSymbolAddress((void**)&p_st1, g_stats1);
    cudaGetSymbolAddress((void**)&p_st3, g_stats3);
    cudaGetSymbolAddress((void**)&p_wt1, g_wt1);
    cudaGetSymbolAddress((void**)&p_wt3, g_wt3);
    cudaGetSymbolAddress((void**)&p_wqkv, g_wqkv);
    cudaGetSymbolAddress((void**)&p_bqkv, g_bqkv);
    cudaGetSymbolAddress((void**)&p_csq, g_csq);
    cudaGetSymbolAddress((void**)&p_wfc1, g_wfc1);
    cudaGetSymbolAddress((void**)&p_bfc1, g_bfc1);
    cudaGetSymbolAddress((void**)&p_csf, g_csf);
    cudaGetSymbolAddress((void**)&p_wpT, g_wpT);
    cudaGetSymbolAddress((void**)&p_fc2T, g_fc2T);

    cudaFuncSetAttribute(gemmk<1,0,KC,C>,   cudaFuncAttributeMaxDynamicSharedMemorySize, DYN_SMEM);
    cudaFuncSetAttribute(gemmk<0,2,C,3*C>,  cudaFuncAttributeMaxDynamicSharedMemorySize, DYN_SMEM);
    cudaFuncSetAttribute(gemmk<0,1,C,C>,    cudaFuncAttributeMaxDynamicSharedMemorySize, DYN_SMEM);
    cudaFuncSetAttribute(gemmk<0,3,C,2*C>,  cudaFuncAttributeMaxDynamicSharedMemorySize, DYN_SMEM);
    cudaFuncSetAttribute(gemmk<0,4,2*C,C>,  cudaFuncAttributeMaxDynamicSharedMemorySize, DYN_SMEM);

    // 1. fused weight preprocessing (one launch)
    prep_all<<<3200, 256>>>(conv1_w, conv3_w, wp, fc2_w,
                            wq, bq, wkv, bkv, ln1_w, ln1_b, ln10_w, ln10_b,
                            fc1_w, fc1_b, ln3_w, ln3_b);

    // 2. convs (implicit im2col)
    gemmk<1,0,KC,C><<<dim3(M / GBM, C / GBN), 256, DYN_SMEM>>>(
        xq, p_wt1, conv1_b, nullptr, nullptr, nullptr, p_x1);
    gemmk<1,0,KC,C><<<dim3(M / GBM, C / GBN), 256, DYN_SMEM>>>(
        xkv, p_wt3, conv3_b, nullptr, nullptr, nullptr, p_x3);

    // 3. LN stats for x1
    ln_stats<<<M / 8, 256>>>(p_x1, p_st1);

    // 4. qkv projection, LN folded into epilogue
    gemmk<0,2,C,3*C><<<dim3(M / GBM, (3 * C) / GBN), 256, DYN_SMEM>>>(
        p_x1, p_wqkv, p_bqkv, p_st1, p_csq, nullptr, p_qkv);

    // 5. neighborhood attention
    nat_attn<<<dim3(14 * 14, HEADS, Bn), 64>>>(rpb);

    // 6. proj + x3 residual
    gemmk<0,1,C,C><<<dim3(M / GBM, C / GBN), 256, DYN_SMEM>>>(
        p_attn, p_wpT, bp, nullptr, nullptr, p_x3, p_att);

    // 7. LN stats for att
    ln_stats<<<M / 8, 256>>>(p_att, p_st3);

    // 8. fc1 + LN epilogue + GELU
    gemmk<0,3,C,2*C><<<dim3(M / GBM, (2 * C) / GBN), 256, DYN_SMEM>>>(
        p_att, p_wfc1, p_bfc1, p_st3, p_csf, nullptr, p_mlp);

    // 9. fc2 + att residual, NCHW store
    gemmk<0,4,2*C,C><<<dim3(M / GBM, C / GBN), 256, DYN_SMEM>>>(
        p_mlp, p_fc2T, fc2_b, nullptr, nullptr, p_att, out);
}